// round 12
// baseline (speedup 1.0000x reference)
#include <cuda_runtime.h>
#include <cuda_bf16.h>

#define NN 100000
#define EE 1000000
#define IN_N 128
#define IN_E 64
#define HFC 128   // H*F = 4*32 = 128 for both node and edge projections

// ---- scratch (static device allocations are the allowed mechanism) ----
__device__ float    g_fni[(size_t)NN * HFC];   // nfeats @ W_ni
__device__ float    g_fnj[(size_t)NN * HFC];   // nfeats @ W_nj
__device__ float    g_h  [(size_t)NN * HFC];   // nfeats @ W_node + b
__device__ float    g_ex [(size_t)EE * 4];     // raw attention logits [E,4]
__device__ float2   g_wp [3 * 64 * HFC];       // k-pair-packed node weights
// CSR over dst
__device__ int      g_cnt   [NN];              // counts, then scatter cursor
__device__ int      g_rowptr[NN + 1];
__device__ int      g_bsum  [512];
__device__ int      g_cidx  [EE];

// packed fp32x2 FMA (2 MACs per issue slot on sm_103a)
__device__ __forceinline__ float2 ffma2(float2 a, float2 b, float2 c) {
    unsigned long long au, bu, cu, du;
    au = reinterpret_cast<unsigned long long&>(a);
    bu = reinterpret_cast<unsigned long long&>(b);
    cu = reinterpret_cast<unsigned long long&>(c);
    asm("fma.rn.f32x2 %0, %1, %2, %3;" : "=l"(du) : "l"(au), "l"(bu), "l"(cu));
    float2 d;
    reinterpret_cast<unsigned long long&>(d) = du;
    return d;
}

__device__ __forceinline__ float compsel(float4 v, int h) {
    return (h == 0) ? v.x : (h == 1) ? v.y : (h == 2) ? v.z : v.w;
}

// ---------------------------------------------------------------------------
// 0) zero CSR counts; pack node weights into float2 k-pairs
// ---------------------------------------------------------------------------
__global__ void setup_kernel(const float* __restrict__ Wni,
                             const float* __restrict__ Wnj,
                             const float* __restrict__ Wn, int N)
{
    int stride = gridDim.x * blockDim.x;
    int i = blockIdx.x * blockDim.x + threadIdx.x;
    for (int j = i; j < N; j += stride) g_cnt[j] = 0;
    // pack: g_wp[m][k2][c] = (W[2k2][c], W[2k2+1][c])
    for (int j = i; j < 3 * 64 * HFC; j += stride) {
        int m = j / (64 * HFC);
        int r = j - m * (64 * HFC);
        int k2 = r / HFC, c = r - k2 * HFC;
        const float* W = (m == 0) ? Wni : (m == 1) ? Wnj : Wn;
        g_wp[j] = make_float2(W[(2 * k2) * HFC + c], W[(2 * k2 + 1) * HFC + c]);
    }
}

// ---- CSR build: count -> 2-level exclusive scan -> scatter -----------------
__global__ void csr_count(const int* __restrict__ dst, int E) {
    int e = blockIdx.x * blockDim.x + threadIdx.x;
    if (e < E) atomicAdd(&g_cnt[dst[e]], 1);
}

__global__ void scan_a(int N) {
    __shared__ int tmp[256];
    int t = threadIdx.x;
    int i = blockIdx.x * 256 + t;
    int v = (i < N) ? g_cnt[i] : 0;
    tmp[t] = v; __syncthreads();
    for (int off = 1; off < 256; off <<= 1) {
        int add = (t >= off) ? tmp[t - off] : 0;
        __syncthreads();
        tmp[t] += add;
        __syncthreads();
    }
    if (i < N) g_rowptr[i] = tmp[t] - v;          // exclusive within block
    if (t == 255) g_bsum[blockIdx.x] = tmp[255];  // block total
}

__global__ void scan_b(int nb) {
    __shared__ int tmp[512];
    int t = threadIdx.x;
    int v = (t < nb) ? g_bsum[t] : 0;
    tmp[t] = v; __syncthreads();
    for (int off = 1; off < 512; off <<= 1) {
        int add = (t >= off) ? tmp[t - off] : 0;
        __syncthreads();
        tmp[t] += add;
        __syncthreads();
    }
    g_bsum[t] = tmp[t] - v;                       // exclusive block offsets
}

__global__ void scan_c(int N, int E) {
    int i = blockIdx.x * 256 + threadIdx.x;
    if (i < N) {
        int r = g_rowptr[i] + g_bsum[blockIdx.x];
        g_rowptr[i] = r;
        g_cnt[i] = r;                              // scatter cursor
    }
    if (i == 0) g_rowptr[N] = E;
}

__global__ void csr_scatter(const int* __restrict__ dst, int E) {
    int e = blockIdx.x * blockDim.x + threadIdx.x;
    if (e < E) {
        int p = atomicAdd(&g_cnt[dst[e]], 1);
        g_cidx[p] = e;
    }
}

// ---------------------------------------------------------------------------
// 1) node projections: f_ni, f_nj, h  (three 128x128 GEMMs fused)
//    128 threads; each thread owns 2 output columns and one 32-row half
// ---------------------------------------------------------------------------
__global__ __launch_bounds__(128) void node_proj(
    const float* __restrict__ x, const float* __restrict__ bn, int N)
{
    __shared__ float xs[64 * IN_N];          // 32 KB, row-major
    const int tid  = threadIdx.x;
    const int half = tid >> 6;               // 0/1 -> rows [0,32) / [32,64)
    const int c2   = tid & 63;               // columns c2 and c2+64
    const int base = blockIdx.x * 64;
    const int nrows = min(64, N - base);

    {   // stage node tile (coalesced, conflict-free)
        const float4* xg = (const float4*)(x + (size_t)base * IN_N);
        float4* xs4 = (float4*)xs;
        int tot4 = nrows * (IN_N / 4);
        for (int i = tid; i < tot4; i += 128) xs4[i] = xg[i];
    }
    __syncthreads();

    const float bias0 = bn[c2];
    const float bias1 = bn[c2 + 64];

    for (int m = 0; m < 3; m++) {
        const float2* Wp = g_wp + m * (64 * HFC);
        float* O   = (m == 0) ? g_fni : (m == 1) ? g_fnj : g_h;
        float b0 = (m == 2) ? bias0 : 0.0f;
        float b1 = (m == 2) ? bias1 : 0.0f;

        for (int g = 0; g < 32; g += 16) {
            int row0 = half * 32 + g;
            if (row0 >= nrows) break;
            float2 acc0[16], acc1[16];
            #pragma unroll
            for (int i = 0; i < 16; i++) {
                acc0[i] = make_float2(0.f, 0.f);
                acc1[i] = make_float2(0.f, 0.f);
            }

            #pragma unroll 4
            for (int k4 = 0; k4 < 32; k4++) {
                float2 wA0 = Wp[(2 * k4) * HFC + c2];
                float2 wB0 = Wp[(2 * k4 + 1) * HFC + c2];
                float2 wA1 = Wp[(2 * k4) * HFC + c2 + 64];
                float2 wB1 = Wp[(2 * k4 + 1) * HFC + c2 + 64];
                #pragma unroll
                for (int i = 0; i < 16; i++) {
                    float4 xv = *(const float4*)&xs[(row0 + i) * IN_N + 4 * k4];
                    float2 lo = make_float2(xv.x, xv.y);
                    float2 hi = make_float2(xv.z, xv.w);
                    acc0[i] = ffma2(lo, wA0, acc0[i]);
                    acc0[i] = ffma2(hi, wB0, acc0[i]);
                    acc1[i] = ffma2(lo, wA1, acc1[i]);
                    acc1[i] = ffma2(hi, wB1, acc1[i]);
                }
            }
            int gn = min(16, nrows - row0);
            for (int i = 0; i < gn; i++) {
                size_t ro = (size_t)(base + row0 + i) * HFC;
                O[ro + c2]      = acc0[i].x + acc0[i].y + b0;
                O[ro + c2 + 64] = acc1[i].x + acc1[i].y + b1;
            }
        }
    }
}

// ---------------------------------------------------------------------------
// 2) per-edge: f_out = lrelu(f_ni[src] + f_nj[dst] + efeats@W_fij + bias),
//    write f_out (streaming), raw logits to g_ex. No atomics.
//    Deep pipeline: efs prefetch depth-1; indices loaded per-thread (broadcast
//    int4 LDG) for tile t+1 right after sync; gathers for t+1 issued after
//    the GEMM of tile t -> full tile of slack to cover L2/DRAM latency.
// ---------------------------------------------------------------------------
#define EPB1 8
__global__ __launch_bounds__(128) void edge_pass1(
    const float* __restrict__ ef, const int* __restrict__ src,
    const int* __restrict__ dst, const float* __restrict__ Wf,
    const float* __restrict__ attn, const float* __restrict__ bias,
    float* __restrict__ fout, int nTiles)
{
    const int c = threadIdx.x;
    const int head = c >> 5;
    const int lane = c & 31;

    float2 wc2[IN_E / 2];
    #pragma unroll
    for (int k2 = 0; k2 < IN_E / 2; k2++)
        wc2[k2] = make_float2(Wf[(2 * k2) * HFC + c], Wf[(2 * k2 + 1) * HFC + c]);
    const float av = attn[head * 32 + lane];
    const float bv = bias[c];

    // EPB1*IN_E/4 = 128 float4 per tile == one per thread
    __shared__ float efs[2][EPB1][IN_E];

    const long long tstep = gridDim.x;
    long long tile = blockIdx.x;
    if (tile >= nTiles) return;

    // ---- prologue: tile0 efs + indices + gathers ----
    float4 pf;
    float fv[EPB1], gv[EPB1];
    {
        long long e0 = tile * EPB1;
        pf = __ldcs(((const float4*)(ef + (size_t)e0 * IN_E)) + c);
        int4 sa = __ldg((const int4*)(src + e0));
        int4 sb = __ldg((const int4*)(src + e0 + 4));
        int4 da = __ldg((const int4*)(dst + e0));
        int4 db = __ldg((const int4*)(dst + e0 + 4));
        int s8[EPB1] = {sa.x, sa.y, sa.z, sa.w, sb.x, sb.y, sb.z, sb.w};
        int d8[EPB1] = {da.x, da.y, da.z, da.w, db.x, db.y, db.z, db.w};
        #pragma unroll
        for (int j = 0; j < EPB1; j++) {
            fv[j] = __ldg(&g_fni[(size_t)s8[j] * HFC + c]);
            gv[j] = __ldg(&g_fnj[(size_t)d8[j] * HFC + c]);
        }
    }

    int buf = 0;
    for (; tile < nTiles; tile += tstep, buf ^= 1) {
        long long e0 = tile * EPB1;
        // commit prefetched efs tile to SMEM
        ((float4*)efs[buf])[c] = pf;
        __syncthreads();

        // prefetch next tile's efs + indices (broadcast int4, 1 wf each)
        long long nt = tile + tstep;
        const bool hasNext = (nt < nTiles);
        int s8[EPB1], d8[EPB1];
        if (hasNext) {
            long long ne0 = nt * EPB1;
            pf = __ldcs(((const float4*)(ef + (size_t)ne0 * IN_E)) + c);
            int4 sa = __ldg((const int4*)(src + ne0));
            int4 sb = __ldg((const int4*)(src + ne0 + 4));
            int4 da = __ldg((const int4*)(dst + ne0));
            int4 db = __ldg((const int4*)(dst + ne0 + 4));
            s8[0] = sa.x; s8[1] = sa.y; s8[2] = sa.z; s8[3] = sa.w;
            s8[4] = sb.x; s8[5] = sb.y; s8[6] = sb.z; s8[7] = sb.w;
            d8[0] = da.x; d8[1] = da.y; d8[2] = da.z; d8[3] = da.w;
            d8[4] = db.x; d8[5] = db.y; d8[6] = db.z; d8[7] = db.w;
        }

        float2 acc[EPB1];
        #pragma unroll
        for (int j = 0; j < EPB1; j++) acc[j] = make_float2(0.f, 0.f);

        #pragma unroll 4
        for (int k4 = 0; k4 < IN_E / 4; k4++) {
            #pragma unroll
            for (int j = 0; j < EPB1; j++) {
                float4 xv = *(const float4*)&efs[buf][j][4 * k4];
                acc[j] = ffma2(make_float2(xv.x, xv.y), wc2[2 * k4], acc[j]);
                acc[j] = ffma2(make_float2(xv.z, xv.w), wc2[2 * k4 + 1], acc[j]);
            }
        }

        // issue NEXT tile's gathers now (indices have arrived during GEMM);
        // they have tail + commit + next GEMM to complete -> latency hidden
        float fvp[EPB1], gvp[EPB1];
        if (hasNext) {
            #pragma unroll
            for (int j = 0; j < EPB1; j++) {
                fvp[j] = __ldg(&g_fni[(size_t)s8[j] * HFC + c]);
                gvp[j] = __ldg(&g_fnj[(size_t)d8[j] * HFC + c]);
            }
        }

        // tail: uses fv/gv issued one tile ago (long since arrived)
        float t[EPB1];
        #pragma unroll
        for (int j = 0; j < EPB1; j++) {
            float v = acc[j].x + acc[j].y + bv + fv[j] + gv[j];
            v = (v > 0.0f) ? v : 0.01f * v;               // leaky relu
            __stcs(&fout[(size_t)(e0 + j) * HFC + c], v); // write-once: stream
            t[j] = v * av;
        }
        #pragma unroll
        for (int o = 16; o > 0; o >>= 1) {
            #pragma unroll
            for (int j = 0; j < EPB1; j++)
                t[j] += __shfl_xor_sync(0xffffffffu, t[j], o);
        }
        if (lane == 0) {
            #pragma unroll
            for (int j = 0; j < EPB1; j++)
                g_ex[(e0 + j) * 4 + head] = t[j];
        }

        if (hasNext) {
            #pragma unroll
            for (int j = 0; j < EPB1; j++) { fv[j] = fvp[j]; gv[j] = gvp[j]; }
        }
    }
}

// remainder edges (E % EPB1); rarely used
__global__ __launch_bounds__(128) void edge_rem(
    const float* __restrict__ ef, const int* __restrict__ src,
    const int* __restrict__ dst, const float* __restrict__ Wf,
    const float* __restrict__ attn, const float* __restrict__ bias,
    float* __restrict__ fout, int e_begin, int E)
{
    const int c = threadIdx.x;
    const int head = c >> 5;
    const int lane = c & 31;
    const float av = attn[head * 32 + lane];
    for (int e = e_begin; e < E; e++) {
        int s = src[e], d = dst[e];
        float acc = bias[c];
        for (int k = 0; k < IN_E; k++)
            acc = fmaf(ef[(size_t)e * IN_E + k], Wf[k * HFC + c], acc);
        float v = acc + g_fni[(size_t)s * HFC + c] + g_fnj[(size_t)d * HFC + c];
        v = (v > 0.0f) ? v : 0.01f * v;
        fout[(size_t)e * HFC + c] = v;
        float t = v * av;
        #pragma unroll
        for (int o = 16; o > 0; o >>= 1)
            t += __shfl_xor_sync(0xffffffffu, t, o);
        if (lane == 0)
            g_ex[(size_t)e * 4 + head] = t;
    }
}

// ---------------------------------------------------------------------------
// 3) fused per-node softmax + aggregation. One warp per node, no atomics.
//    h_out[d] = sum_e softmax_e(logit) * h[src[e]]   (per head)
// ---------------------------------------------------------------------------
#define AGG_WARPS 8
#define AGG_CAP 128
__global__ __launch_bounds__(256) void agg(
    const int* __restrict__ src, float* __restrict__ hout, int N)
{
    __shared__ float sa[AGG_WARPS][AGG_CAP * 4];   // exp values per edge/head
    __shared__ int   ss[AGG_WARPS][AGG_CAP];       // src ids
    const int w = threadIdx.x >> 5;
    const int lane = threadIdx.x & 31;
    const int d = blockIdx.x * AGG_WARPS + w;
    if (d >= N) return;

    const int start = g_rowptr[d];
    const int deg = g_rowptr[d + 1] - start;
    const float NEG = __int_as_float(0xff800000);   // -inf

    // phase 1a: per-head max over incoming edges
    float4 m4 = make_float4(NEG, NEG, NEG, NEG);
    for (int t = lane; t < deg; t += 32) {
        int eid = g_cidx[start + t];
        float4 l4 = *(const float4*)&g_ex[(size_t)eid * 4];
        m4.x = fmaxf(m4.x, l4.x); m4.y = fmaxf(m4.y, l4.y);
        m4.z = fmaxf(m4.z, l4.z); m4.w = fmaxf(m4.w, l4.w);
    }
    #pragma unroll
    for (int o = 16; o > 0; o >>= 1) {
        m4.x = fmaxf(m4.x, __shfl_xor_sync(0xffffffffu, m4.x, o));
        m4.y = fmaxf(m4.y, __shfl_xor_sync(0xffffffffu, m4.y, o));
        m4.z = fmaxf(m4.z, __shfl_xor_sync(0xffffffffu, m4.z, o));
        m4.w = fmaxf(m4.w, __shfl_xor_sync(0xffffffffu, m4.w, o));
    }

    // phase 1b: exp + sum, stash exp values and src ids in SMEM
    float4 s4 = make_float4(0.f, 0.f, 0.f, 0.f);
    for (int t = lane; t < deg; t += 32) {
        int eid = g_cidx[start + t];
        float4 l4 = *(const float4*)&g_ex[(size_t)eid * 4];
        float4 e4 = make_float4(__expf(l4.x - m4.x), __expf(l4.y - m4.y),
                                __expf(l4.z - m4.z), __expf(l4.w - m4.w));
        s4.x += e4.x; s4.y += e4.y; s4.z += e4.z; s4.w += e4.w;
        if (t < AGG_CAP) {
            *(float4*)&sa[w][t * 4] = e4;
            ss[w][t] = src[eid];
        }
    }
    #pragma unroll
    for (int o = 16; o > 0; o >>= 1) {
        s4.x += __shfl_xor_sync(0xffffffffu, s4.x, o);
        s4.y += __shfl_xor_sync(0xffffffffu, s4.y, o);
        s4.z += __shfl_xor_sync(0xffffffffu, s4.z, o);
        s4.w += __shfl_xor_sync(0xffffffffu, s4.w, o);
    }
    __syncwarp();

    const int head = lane >> 3;
    const float inv = __fdividef(1.0f, compsel(s4, head));
    const float mh = compsel(m4, head);

    // phase 2: aggregate h[src]*a with MLP-4 grouped gathers
    float4 acc = make_float4(0.f, 0.f, 0.f, 0.f);
    for (int t0 = 0; t0 < deg; t0 += 4) {
        int n = min(4, deg - t0);
        float a[4]; int s[4];
        #pragma unroll
        for (int r = 0; r < 4; r++) {
            if (r < n) {
                int t = t0 + r;
                if (t < AGG_CAP) {
                    a[r] = sa[w][t * 4 + head] * inv;
                    s[r] = ss[w][t];
                } else {                           // overflow fallback (rare)
                    int eid = g_cidx[start + t];
                    float4 l4 = *(const float4*)&g_ex[(size_t)eid * 4];
                    a[r] = __expf(compsel(l4, head) - mh) * inv;
                    s[r] = src[eid];
                }
            }
        }
        float4 hv[4];
        #pragma unroll
        for (int r = 0; r < 4; r++)
            if (r < n) hv[r] = __ldg(&((const float4*)(g_h + (size_t)s[r] * HFC))[lane]);
        #pragma unroll
        for (int r = 0; r < 4; r++) {
            if (r < n) {
                acc.x = fmaf(hv[r].x, a[r], acc.x);
                acc.y = fmaf(hv[r].y, a[r], acc.y);
                acc.z = fmaf(hv[r].z, a[r], acc.z);
                acc.w = fmaf(hv[r].w, a[r], acc.w);
            }
        }
    }
    ((float4*)(hout + (size_t)d * HFC))[lane] = acc;
}

// ---------------------------------------------------------------------------
extern "C" void kernel_launch(void* const* d_in, const int* in_sizes, int n_in,
                              void* d_out, int out_size)
{
    const float* nfeats = (const float*)d_in[0];
    const float* efeats = (const float*)d_in[1];
    const int*   src    = (const int*)d_in[2];
    const int*   dst    = (const int*)d_in[3];
    const float* W_node = (const float*)d_in[4];
    const float* b_node = (const float*)d_in[5];
    const float* W_ni   = (const float*)d_in[6];
    const float* W_nj   = (const float*)d_in[7];
    const float* W_fij  = (const float*)d_in[8];
    const float* attn   = (const float*)d_in[9];
    const float* bias   = (const float*)d_in[10];

    const int N = in_sizes[0] / IN_N;   // 100000
    const int E = in_sizes[2];          // 1000000

    float* h_out = (float*)d_out;                       // [N, 128]
    float* f_out = (float*)d_out + (size_t)N * HFC;     // [E, 128]

    int nb = (N + 255) / 256;
    int nTiles = E / EPB1;

    // launch order chosen so edge_pass1 is the 4th launch (ncu -s capture slot)
    setup_kernel<<<512, 256>>>(W_ni, W_nj, W_node, N);            // 1
    node_proj<<<(N + 63) / 64, 128>>>(nfeats, b_node, N);         // 2
    csr_count<<<(E + 255) / 256, 256>>>(dst, E);                  // 3
    if (nTiles > 0)
        edge_pass1<<<148 * 8, 128>>>(efeats, src, dst, W_fij,     // 4
                                     attn, bias, f_out, nTiles);
    scan_a     <<<nb, 256>>>(N);                                  // 5
    scan_b     <<<1, 512>>>(nb);                                  // 6
    scan_c     <<<nb, 256>>>(N, E);                               // 7
    csr_scatter<<<(E + 255) / 256, 256>>>(dst, E);                // 8
    if (E % EPB1)
        edge_rem<<<1, 128>>>(efeats, src, dst, W_fij, attn, bias,
                             f_out, nTiles * EPB1, E);
    agg<<<(N + AGG_WARPS - 1) / AGG_WARPS, 256>>>(src, h_out, N); // 9
}

// round 15
// speedup vs baseline: 1.1964x; 1.1964x over previous
#include <cuda_runtime.h>
#include <cuda_bf16.h>

#define NN 100000
#define EE 1000000
#define IN_N 128
#define IN_E 64
#define HFC 128   // H*F = 4*32 = 128 for both node and edge projections

// ---- scratch (static device allocations are the allowed mechanism) ----
__device__ float    g_fni[(size_t)NN * HFC];   // nfeats @ W_ni
__device__ float    g_fnj[(size_t)NN * HFC];   // nfeats @ W_nj
__device__ float    g_h  [(size_t)NN * HFC];   // nfeats @ W_node + b
__device__ float    g_ex [(size_t)EE * 4];     // raw attention logits [E,4]
__device__ float4   g_wp4[3 * 32 * HFC];       // k4-packed node weights
__device__ float4   g_wfp[16 * HFC];           // k4-packed edge weights
// CSR over dst
__device__ int      g_cnt   [NN];              // counts, then scatter cursor
__device__ int      g_rowptr[NN + 1];
__device__ int      g_bsum  [512];
__device__ int      g_cidx  [EE];

// packed fp32x2 FMA (2 MACs per issue slot on sm_103a)
__device__ __forceinline__ float2 ffma2(float2 a, float2 b, float2 c) {
    unsigned long long au, bu, cu, du;
    au = reinterpret_cast<unsigned long long&>(a);
    bu = reinterpret_cast<unsigned long long&>(b);
    cu = reinterpret_cast<unsigned long long&>(c);
    asm("fma.rn.f32x2 %0, %1, %2, %3;" : "=l"(du) : "l"(au), "l"(bu), "l"(cu));
    float2 d;
    reinterpret_cast<unsigned long long&>(d) = du;
    return d;
}

__device__ __forceinline__ float compsel(float4 v, int h) {
    return (h == 0) ? v.x : (h == 1) ? v.y : (h == 2) ? v.z : v.w;
}

// ---------------------------------------------------------------------------
// 0) zero CSR counts; pack weights into float4 k-quads
// ---------------------------------------------------------------------------
__global__ void setup_kernel(const float* __restrict__ Wni,
                             const float* __restrict__ Wnj,
                             const float* __restrict__ Wn,
                             const float* __restrict__ Wf, int N)
{
    int stride = gridDim.x * blockDim.x;
    int i = blockIdx.x * blockDim.x + threadIdx.x;
    for (int j = i; j < N; j += stride) g_cnt[j] = 0;
    // node weights: g_wp4[m][k4][c] = (W[4k4][c],W[4k4+1][c],W[4k4+2][c],W[4k4+3][c])
    for (int j = i; j < 3 * 32 * HFC; j += stride) {
        int m = j / (32 * HFC);
        int r = j - m * (32 * HFC);
        int k4 = r / HFC, c = r - k4 * HFC;
        const float* W = (m == 0) ? Wni : (m == 1) ? Wnj : Wn;
        g_wp4[j] = make_float4(W[(4 * k4 + 0) * HFC + c], W[(4 * k4 + 1) * HFC + c],
                               W[(4 * k4 + 2) * HFC + c], W[(4 * k4 + 3) * HFC + c]);
    }
    // edge weights: g_wfp[k4][c]
    for (int j = i; j < 16 * HFC; j += stride) {
        int k4 = j / HFC, c = j - k4 * HFC;
        g_wfp[j] = make_float4(Wf[(4 * k4 + 0) * HFC + c], Wf[(4 * k4 + 1) * HFC + c],
                               Wf[(4 * k4 + 2) * HFC + c], Wf[(4 * k4 + 3) * HFC + c]);
    }
}

// ---- CSR build: count -> 2-level exclusive scan -> scatter -----------------
__global__ void csr_count(const int* __restrict__ dst, int E) {
    int e = blockIdx.x * blockDim.x + threadIdx.x;
    if (e < E) atomicAdd(&g_cnt[dst[e]], 1);
}

__global__ void scan_a(int N) {
    __shared__ int tmp[256];
    int t = threadIdx.x;
    int i = blockIdx.x * 256 + t;
    int v = (i < N) ? g_cnt[i] : 0;
    tmp[t] = v; __syncthreads();
    for (int off = 1; off < 256; off <<= 1) {
        int add = (t >= off) ? tmp[t - off] : 0;
        __syncthreads();
        tmp[t] += add;
        __syncthreads();
    }
    if (i < N) g_rowptr[i] = tmp[t] - v;          // exclusive within block
    if (t == 255) g_bsum[blockIdx.x] = tmp[255];  // block total
}

__global__ void scan_b(int nb) {
    __shared__ int tmp[512];
    int t = threadIdx.x;
    int v = (t < nb) ? g_bsum[t] : 0;
    tmp[t] = v; __syncthreads();
    for (int off = 1; off < 512; off <<= 1) {
        int add = (t >= off) ? tmp[t - off] : 0;
        __syncthreads();
        tmp[t] += add;
        __syncthreads();
    }
    g_bsum[t] = tmp[t] - v;                       // exclusive block offsets
}

__global__ void scan_c(int N, int E) {
    int i = blockIdx.x * 256 + threadIdx.x;
    if (i < N) {
        int r = g_rowptr[i] + g_bsum[blockIdx.x];
        g_rowptr[i] = r;
        g_cnt[i] = r;                              // scatter cursor
    }
    if (i == 0) g_rowptr[N] = E;
}

__global__ void csr_scatter(const int* __restrict__ dst, int E) {
    int e = blockIdx.x * blockDim.x + threadIdx.x;
    if (e < E) {
        int p = atomicAdd(&g_cnt[dst[e]], 1);
        g_cidx[p] = e;
    }
}

// ---------------------------------------------------------------------------
// 1) node projections: f_ni, f_nj, h  (three 128x128 GEMMs fused)
//    128 threads; each thread owns 2 output columns and one 32-row half
// ---------------------------------------------------------------------------
__global__ __launch_bounds__(128) void node_proj(
    const float* __restrict__ x, const float* __restrict__ bn, int N)
{
    __shared__ float xs[64 * IN_N];          // 32 KB, row-major
    const int tid  = threadIdx.x;
    const int half = tid >> 6;               // 0/1 -> rows [0,32) / [32,64)
    const int c2   = tid & 63;               // columns c2 and c2+64
    const int base = blockIdx.x * 64;
    const int nrows = min(64, N - base);

    {   // stage node tile (coalesced, conflict-free)
        const float4* xg = (const float4*)(x + (size_t)base * IN_N);
        float4* xs4 = (float4*)xs;
        int tot4 = nrows * (IN_N / 4);
        for (int i = tid; i < tot4; i += 128) xs4[i] = xg[i];
    }
    __syncthreads();

    const float bias0 = bn[c2];
    const float bias1 = bn[c2 + 64];

    for (int m = 0; m < 3; m++) {
        const float4* Wp = g_wp4 + m * (32 * HFC);
        float* O   = (m == 0) ? g_fni : (m == 1) ? g_fnj : g_h;
        float b0 = (m == 2) ? bias0 : 0.0f;
        float b1 = (m == 2) ? bias1 : 0.0f;

        for (int g = 0; g < 32; g += 16) {
            int row0 = half * 32 + g;
            if (row0 >= nrows) break;
            float2 acc0[16], acc1[16];
            #pragma unroll
            for (int i = 0; i < 16; i++) {
                acc0[i] = make_float2(0.f, 0.f);
                acc1[i] = make_float2(0.f, 0.f);
            }

            #pragma unroll 4
            for (int k4 = 0; k4 < 32; k4++) {
                float4 w0 = __ldg(&Wp[k4 * HFC + c2]);
                float4 w1 = __ldg(&Wp[k4 * HFC + c2 + 64]);
                #pragma unroll
                for (int i = 0; i < 16; i++) {
                    float4 xv = *(const float4*)&xs[(row0 + i) * IN_N + 4 * k4];
                    float2 lo = make_float2(xv.x, xv.y);
                    float2 hi = make_float2(xv.z, xv.w);
                    acc0[i] = ffma2(lo, make_float2(w0.x, w0.y), acc0[i]);
                    acc0[i] = ffma2(hi, make_float2(w0.z, w0.w), acc0[i]);
                    acc1[i] = ffma2(lo, make_float2(w1.x, w1.y), acc1[i]);
                    acc1[i] = ffma2(hi, make_float2(w1.z, w1.w), acc1[i]);
                }
            }
            int gn = min(16, nrows - row0);
            for (int i = 0; i < gn; i++) {
                size_t ro = (size_t)(base + row0 + i) * HFC;
                O[ro + c2]      = acc0[i].x + acc0[i].y + b0;
                O[ro + c2 + 64] = acc1[i].x + acc1[i].y + b1;
            }
        }
    }
}

// ---------------------------------------------------------------------------
// 2) per-edge: f_out = lrelu(f_ni[src] + f_nj[dst] + efeats@W_fij + bias),
//    write f_out (streaming), raw logits to g_ex. No atomics.
//    R11 pipeline (depth-1 efs prefetch; gathers pre-GEMM) + explicit
//    float4-packed W LDGs (no register-array remat).
// ---------------------------------------------------------------------------
#define EPB1 8
__global__ __launch_bounds__(128) void edge_pass1(
    const float* __restrict__ ef, const int* __restrict__ src,
    const int* __restrict__ dst,
    const float* __restrict__ attn, const float* __restrict__ bias,
    float* __restrict__ fout, int nTiles)
{
    const int c = threadIdx.x;
    const int head = c >> 5;
    const int lane = c & 31;

    const float av = attn[head * 32 + lane];
    const float bv = bias[c];

    // EPB1*IN_E/4 = 128 float4 per tile == one per thread
    __shared__ float efs[2][EPB1][IN_E];
    __shared__ int sidx[2][EPB1], didx[2][EPB1];

    const long long tstep = gridDim.x;
    long long tile = blockIdx.x;
    if (tile >= nTiles) return;

    // prefetch first tile into registers
    float4 pf; int ps = 0, pd = 0;
    {
        long long e0 = tile * EPB1;
        pf = __ldcs(((const float4*)(ef + (size_t)e0 * IN_E)) + c);
        if (c < EPB1) ps = src[e0 + c];
        else if (c >= 32 && c < 32 + EPB1) pd = dst[e0 + (c - 32)];
    }

    int buf = 0;
    for (; tile < nTiles; tile += tstep, buf ^= 1) {
        long long e0 = tile * EPB1;
        // commit prefetched tile to SMEM
        ((float4*)efs[buf])[c] = pf;
        if (c < EPB1) sidx[buf][c] = ps;
        else if (c >= 32 && c < 32 + EPB1) didx[buf][c - 32] = pd;
        __syncthreads();

        // issue next tile's prefetch (overlaps gathers + GEMM below)
        long long nt = tile + tstep;
        if (nt < nTiles) {
            long long ne0 = nt * EPB1;
            pf = __ldcs(((const float4*)(ef + (size_t)ne0 * IN_E)) + c);
            if (c < EPB1) ps = src[ne0 + c];
            else if (c >= 32 && c < 32 + EPB1) pd = dst[ne0 + (c - 32)];
        }

        // issue all fni/fnj gathers up-front (MLP 16, overlap the GEMM)
        float fv[EPB1], gv[EPB1];
        #pragma unroll
        for (int j = 0; j < EPB1; j++) {
            fv[j] = __ldg(&g_fni[(size_t)sidx[buf][j] * HFC + c]);
            gv[j] = __ldg(&g_fnj[(size_t)didx[buf][j] * HFC + c]);
        }

        float2 acc[EPB1];
        #pragma unroll
        for (int j = 0; j < EPB1; j++) acc[j] = make_float2(0.f, 0.f);

        #pragma unroll 4
        for (int k4 = 0; k4 < IN_E / 4; k4++) {
            float4 w4 = __ldg(&g_wfp[k4 * HFC + c]);   // L1-hot packed W column
            float2 wA = make_float2(w4.x, w4.y);
            float2 wB = make_float2(w4.z, w4.w);
            #pragma unroll
            for (int j = 0; j < EPB1; j++) {
                float4 xv = *(const float4*)&efs[buf][j][4 * k4];
                acc[j] = ffma2(make_float2(xv.x, xv.y), wA, acc[j]);
                acc[j] = ffma2(make_float2(xv.z, xv.w), wB, acc[j]);
            }
        }

        // tail: compute + store all v, then interleaved shuffle reductions
        float t[EPB1];
        #pragma unroll
        for (int j = 0; j < EPB1; j++) {
            float v = acc[j].x + acc[j].y + bv + fv[j] + gv[j];
            v = (v > 0.0f) ? v : 0.01f * v;               // leaky relu
            __stcs(&fout[(size_t)(e0 + j) * HFC + c], v); // write-once: stream
            t[j] = v * av;
        }
        #pragma unroll
        for (int o = 16; o > 0; o >>= 1) {
            #pragma unroll
            for (int j = 0; j < EPB1; j++)
                t[j] += __shfl_xor_sync(0xffffffffu, t[j], o);
        }
        if (lane == 0) {
            #pragma unroll
            for (int j = 0; j < EPB1; j++)
                g_ex[(e0 + j) * 4 + head] = t[j];
        }
    }
}

// remainder edges (E % EPB1); rarely used
__global__ __launch_bounds__(128) void edge_rem(
    const float* __restrict__ ef, const int* __restrict__ src,
    const int* __restrict__ dst, const float* __restrict__ Wf,
    const float* __restrict__ attn, const float* __restrict__ bias,
    float* __restrict__ fout, int e_begin, int E)
{
    const int c = threadIdx.x;
    const int head = c >> 5;
    const int lane = c & 31;
    const float av = attn[head * 32 + lane];
    for (int e = e_begin; e < E; e++) {
        int s = src[e], d = dst[e];
        float acc = bias[c];
        for (int k = 0; k < IN_E; k++)
            acc = fmaf(ef[(size_t)e * IN_E + k], Wf[k * HFC + c], acc);
        float v = acc + g_fni[(size_t)s * HFC + c] + g_fnj[(size_t)d * HFC + c];
        v = (v > 0.0f) ? v : 0.01f * v;
        fout[(size_t)e * HFC + c] = v;
        float t = v * av;
        #pragma unroll
        for (int o = 16; o > 0; o >>= 1)
            t += __shfl_xor_sync(0xffffffffu, t, o);
        if (lane == 0)
            g_ex[(size_t)e * 4 + head] = t;
    }
}

// ---------------------------------------------------------------------------
// 3) fused per-node softmax + aggregation. One warp per node, no atomics.
//    h_out[d] = sum_e softmax_e(logit) * h[src[e]]   (per head)
// ---------------------------------------------------------------------------
#define AGG_WARPS 8
#define AGG_CAP 128
__global__ __launch_bounds__(256) void agg(
    const int* __restrict__ src, float* __restrict__ hout, int N)
{
    __shared__ float sa[AGG_WARPS][AGG_CAP * 4];   // exp values per edge/head
    __shared__ int   ss[AGG_WARPS][AGG_CAP];       // src ids
    const int w = threadIdx.x >> 5;
    const int lane = threadIdx.x & 31;
    const int d = blockIdx.x * AGG_WARPS + w;
    if (d >= N) return;

    const int start = g_rowptr[d];
    const int deg = g_rowptr[d + 1] - start;
    const float NEG = __int_as_float(0xff800000);   // -inf

    // phase 1a: per-head max over incoming edges
    float4 m4 = make_float4(NEG, NEG, NEG, NEG);
    for (int t = lane; t < deg; t += 32) {
        int eid = g_cidx[start + t];
        float4 l4 = *(const float4*)&g_ex[(size_t)eid * 4];
        m4.x = fmaxf(m4.x, l4.x); m4.y = fmaxf(m4.y, l4.y);
        m4.z = fmaxf(m4.z, l4.z); m4.w = fmaxf(m4.w, l4.w);
    }
    #pragma unroll
    for (int o = 16; o > 0; o >>= 1) {
        m4.x = fmaxf(m4.x, __shfl_xor_sync(0xffffffffu, m4.x, o));
        m4.y = fmaxf(m4.y, __shfl_xor_sync(0xffffffffu, m4.y, o));
        m4.z = fmaxf(m4.z, __shfl_xor_sync(0xffffffffu, m4.z, o));
        m4.w = fmaxf(m4.w, __shfl_xor_sync(0xffffffffu, m4.w, o));
    }

    // phase 1b: exp + sum, stash exp values and src ids in SMEM
    float4 s4 = make_float4(0.f, 0.f, 0.f, 0.f);
    for (int t = lane; t < deg; t += 32) {
        int eid = g_cidx[start + t];
        float4 l4 = *(const float4*)&g_ex[(size_t)eid * 4];
        float4 e4 = make_float4(__expf(l4.x - m4.x), __expf(l4.y - m4.y),
                                __expf(l4.z - m4.z), __expf(l4.w - m4.w));
        s4.x += e4.x; s4.y += e4.y; s4.z += e4.z; s4.w += e4.w;
        if (t < AGG_CAP) {
            *(float4*)&sa[w][t * 4] = e4;
            ss[w][t] = src[eid];
        }
    }
    #pragma unroll
    for (int o = 16; o > 0; o >>= 1) {
        s4.x += __shfl_xor_sync(0xffffffffu, s4.x, o);
        s4.y += __shfl_xor_sync(0xffffffffu, s4.y, o);
        s4.z += __shfl_xor_sync(0xffffffffu, s4.z, o);
        s4.w += __shfl_xor_sync(0xffffffffu, s4.w, o);
    }
    __syncwarp();

    const int head = lane >> 3;
    const float inv = __fdividef(1.0f, compsel(s4, head));
    const float mh = compsel(m4, head);

    // phase 2: aggregate h[src]*a with MLP-4 grouped gathers
    float4 acc = make_float4(0.f, 0.f, 0.f, 0.f);
    for (int t0 = 0; t0 < deg; t0 += 4) {
        int n = min(4, deg - t0);
        float a[4]; int s[4];
        #pragma unroll
        for (int r = 0; r < 4; r++) {
            if (r < n) {
                int t = t0 + r;
                if (t < AGG_CAP) {
                    a[r] = sa[w][t * 4 + head] * inv;
                    s[r] = ss[w][t];
                } else {                           // overflow fallback (rare)
                    int eid = g_cidx[start + t];
                    float4 l4 = *(const float4*)&g_ex[(size_t)eid * 4];
                    a[r] = __expf(compsel(l4, head) - mh) * inv;
                    s[r] = src[eid];
                }
            }
        }
        float4 hv[4];
        #pragma unroll
        for (int r = 0; r < 4; r++)
            if (r < n) hv[r] = __ldg(&((const float4*)(g_h + (size_t)s[r] * HFC))[lane]);
        #pragma unroll
        for (int r = 0; r < 4; r++) {
            if (r < n) {
                acc.x = fmaf(hv[r].x, a[r], acc.x);
                acc.y = fmaf(hv[r].y, a[r], acc.y);
                acc.z = fmaf(hv[r].z, a[r], acc.z);
                acc.w = fmaf(hv[r].w, a[r], acc.w);
            }
        }
    }
    ((float4*)(hout + (size_t)d * HFC))[lane] = acc;
}

// ---------------------------------------------------------------------------
extern "C" void kernel_launch(void* const* d_in, const int* in_sizes, int n_in,
                              void* d_out, int out_size)
{
    const float* nfeats = (const float*)d_in[0];
    const float* efeats = (const float*)d_in[1];
    const int*   src    = (const int*)d_in[2];
    const int*   dst    = (const int*)d_in[3];
    const float* W_node = (const float*)d_in[4];
    const float* b_node = (const float*)d_in[5];
    const float* W_ni   = (const float*)d_in[6];
    const float* W_nj   = (const float*)d_in[7];
    const float* W_fij  = (const float*)d_in[8];
    const float* attn   = (const float*)d_in[9];
    const float* bias   = (const float*)d_in[10];

    const int N = in_sizes[0] / IN_N;   // 100000
    const int E = in_sizes[2];          // 1000000

    float* h_out = (float*)d_out;                       // [N, 128]
    float* f_out = (float*)d_out + (size_t)N * HFC;     // [E, 128]

    int nb = (N + 255) / 256;
    int nTiles = E / EPB1;

    // launch order chosen so edge_pass1 is the 4th launch (ncu -s capture slot)
    setup_kernel<<<512, 256>>>(W_ni, W_nj, W_node, W_fij, N);     // 1
    node_proj<<<(N + 63) / 64, 128>>>(nfeats, b_node, N);         // 2
    csr_count<<<(E + 255) / 256, 256>>>(dst, E);                  // 3
    if (nTiles > 0)
        edge_pass1<<<148 * 10, 128>>>(efeats, src, dst,           // 4
                                      attn, bias, f_out, nTiles);
    scan_a     <<<nb, 256>>>(N);                                  // 5
    scan_b     <<<1, 512>>>(nb);                                  // 6
    scan_c     <<<nb, 256>>>(N, E);                               // 7
    csr_scatter<<<(E + 255) / 256, 256>>>(dst, E);                // 8
    if (E % EPB1)
        edge_rem<<<1, 128>>>(efeats, src, dst, W_fij, attn, bias,
                             f_out, nTiles * EPB1, E);
    agg<<<(N + AGG_WARPS - 1) / AGG_WARPS, 256>>>(src, h_out, N); // 9
}

// round 16
// speedup vs baseline: 1.2919x; 1.0798x over previous
#include <cuda_runtime.h>
#include <cuda_bf16.h>

#define NN 100000
#define EE 1000000
#define IN_N 128
#define IN_E 64
#define HFC 128   // H*F = 4*32 = 128 for both node and edge projections

// ---- scratch (static device allocations are the allowed mechanism) ----
__device__ float    g_fni[(size_t)NN * HFC];   // nfeats @ W_ni
__device__ float    g_fnj[(size_t)NN * HFC];   // nfeats @ W_nj
__device__ float    g_h  [(size_t)NN * HFC];   // nfeats @ W_node + b
__device__ float    g_fe [(size_t)EE * HFC];   // efeats @ W_fij (dense GEMM out)
__device__ float    g_ex [(size_t)EE * 4];     // raw attention logits [E,4]
__device__ float4   g_wp4[3 * 32 * HFC];       // k4-packed node weights
// CSR over dst
__device__ int      g_cnt   [NN];              // counts, then scatter cursor
__device__ int      g_rowptr[NN + 1];
__device__ int      g_bsum  [512];
__device__ int      g_cidx  [EE];

// packed fp32x2 FMA (2 MACs per issue slot on sm_103a)
__device__ __forceinline__ float2 ffma2(float2 a, float2 b, float2 c) {
    unsigned long long au, bu, cu, du;
    au = reinterpret_cast<unsigned long long&>(a);
    bu = reinterpret_cast<unsigned long long&>(b);
    cu = reinterpret_cast<unsigned long long&>(c);
    asm("fma.rn.f32x2 %0, %1, %2, %3;" : "=l"(du) : "l"(au), "l"(bu), "l"(cu));
    float2 d;
    reinterpret_cast<unsigned long long&>(d) = du;
    return d;
}

__device__ __forceinline__ float compsel(float4 v, int h) {
    return (h == 0) ? v.x : (h == 1) ? v.y : (h == 2) ? v.z : v.w;
}

__device__ __forceinline__ float lrelu(float v) {
    return (v > 0.0f) ? v : 0.01f * v;
}

// ---------------------------------------------------------------------------
// 0) zero CSR counts; pack node weights into float4 k-quads
// ---------------------------------------------------------------------------
__global__ void setup_kernel(const float* __restrict__ Wni,
                             const float* __restrict__ Wnj,
                             const float* __restrict__ Wn, int N)
{
    int stride = gridDim.x * blockDim.x;
    int i = blockIdx.x * blockDim.x + threadIdx.x;
    for (int j = i; j < N; j += stride) g_cnt[j] = 0;
    // node weights: g_wp4[m][k4][c] = (W[4k4][c],W[4k4+1][c],W[4k4+2][c],W[4k4+3][c])
    for (int j = i; j < 3 * 32 * HFC; j += stride) {
        int m = j / (32 * HFC);
        int r = j - m * (32 * HFC);
        int k4 = r / HFC, c = r - k4 * HFC;
        const float* W = (m == 0) ? Wni : (m == 1) ? Wnj : Wn;
        g_wp4[j] = make_float4(W[(4 * k4 + 0) * HFC + c], W[(4 * k4 + 1) * HFC + c],
                               W[(4 * k4 + 2) * HFC + c], W[(4 * k4 + 3) * HFC + c]);
    }
}

// ---- CSR build: count -> 2-level exclusive scan -> scatter -----------------
__global__ void csr_count(const int* __restrict__ dst, int E) {
    int e = blockIdx.x * blockDim.x + threadIdx.x;
    if (e < E) atomicAdd(&g_cnt[dst[e]], 1);
}

__global__ void scan_a(int N) {
    __shared__ int tmp[256];
    int t = threadIdx.x;
    int i = blockIdx.x * 256 + t;
    int v = (i < N) ? g_cnt[i] : 0;
    tmp[t] = v; __syncthreads();
    for (int off = 1; off < 256; off <<= 1) {
        int add = (t >= off) ? tmp[t - off] : 0;
        __syncthreads();
        tmp[t] += add;
        __syncthreads();
    }
    if (i < N) g_rowptr[i] = tmp[t] - v;          // exclusive within block
    if (t == 255) g_bsum[blockIdx.x] = tmp[255];  // block total
}

__global__ void scan_b(int nb) {
    __shared__ int tmp[512];
    int t = threadIdx.x;
    int v = (t < nb) ? g_bsum[t] : 0;
    tmp[t] = v; __syncthreads();
    for (int off = 1; off < 512; off <<= 1) {
        int add = (t >= off) ? tmp[t - off] : 0;
        __syncthreads();
        tmp[t] += add;
        __syncthreads();
    }
    g_bsum[t] = tmp[t] - v;                       // exclusive block offsets
}

__global__ void scan_c(int N, int E) {
    int i = blockIdx.x * 256 + threadIdx.x;
    if (i < N) {
        int r = g_rowptr[i] + g_bsum[blockIdx.x];
        g_rowptr[i] = r;
        g_cnt[i] = r;                              // scatter cursor
    }
    if (i == 0) g_rowptr[N] = E;
}

__global__ void csr_scatter(const int* __restrict__ dst, int E) {
    int e = blockIdx.x * blockDim.x + threadIdx.x;
    if (e < E) {
        int p = atomicAdd(&g_cnt[dst[e]], 1);
        g_cidx[p] = e;
    }
}

// ---------------------------------------------------------------------------
// 1) node projections: f_ni, f_nj, h  (three 128x128 GEMMs fused)
//    128 threads; each thread owns 2 output columns and one 32-row half
// ---------------------------------------------------------------------------
__global__ __launch_bounds__(128) void node_proj(
    const float* __restrict__ x, const float* __restrict__ bn, int N)
{
    __shared__ float xs[64 * IN_N];          // 32 KB, row-major
    const int tid  = threadIdx.x;
    const int half = tid >> 6;               // 0/1 -> rows [0,32) / [32,64)
    const int c2   = tid & 63;               // columns c2 and c2+64
    const int base = blockIdx.x * 64;
    const int nrows = min(64, N - base);

    {   // stage node tile (coalesced, conflict-free)
        const float4* xg = (const float4*)(x + (size_t)base * IN_N);
        float4* xs4 = (float4*)xs;
        int tot4 = nrows * (IN_N / 4);
        for (int i = tid; i < tot4; i += 128) xs4[i] = xg[i];
    }
    __syncthreads();

    const float bias0 = bn[c2];
    const float bias1 = bn[c2 + 64];

    for (int m = 0; m < 3; m++) {
        const float4* Wp = g_wp4 + m * (32 * HFC);
        float* O   = (m == 0) ? g_fni : (m == 1) ? g_fnj : g_h;
        float b0 = (m == 2) ? bias0 : 0.0f;
        float b1 = (m == 2) ? bias1 : 0.0f;

        for (int g = 0; g < 32; g += 16) {
            int row0 = half * 32 + g;
            if (row0 >= nrows) break;
            float2 acc0[16], acc1[16];
            #pragma unroll
            for (int i = 0; i < 16; i++) {
                acc0[i] = make_float2(0.f, 0.f);
                acc1[i] = make_float2(0.f, 0.f);
            }

            #pragma unroll 4
            for (int k4 = 0; k4 < 32; k4++) {
                float4 w0 = __ldg(&Wp[k4 * HFC + c2]);
                float4 w1 = __ldg(&Wp[k4 * HFC + c2 + 64]);
                #pragma unroll
                for (int i = 0; i < 16; i++) {
                    float4 xv = *(const float4*)&xs[(row0 + i) * IN_N + 4 * k4];
                    float2 lo = make_float2(xv.x, xv.y);
                    float2 hi = make_float2(xv.z, xv.w);
                    acc0[i] = ffma2(lo, make_float2(w0.x, w0.y), acc0[i]);
                    acc0[i] = ffma2(hi, make_float2(w0.z, w0.w), acc0[i]);
                    acc1[i] = ffma2(lo, make_float2(w1.x, w1.y), acc1[i]);
                    acc1[i] = ffma2(hi, make_float2(w1.z, w1.w), acc1[i]);
                }
            }
            int gn = min(16, nrows - row0);
            for (int i = 0; i < gn; i++) {
                size_t ro = (size_t)(base + row0 + i) * HFC;
                O[ro + c2]      = acc0[i].x + acc0[i].y + b0;
                O[ro + c2 + 64] = acc1[i].x + acc1[i].y + b1;
            }
        }
    }
}

// ---------------------------------------------------------------------------
// 2a) dense edge GEMM: g_fe = efeats @ W_fij   [E,64] x [64,128]
//     256 threads; 64 edges per block; thread owns 4 consecutive cols x 8 rows
//     -> xv LDS broadcast feeds 8 FFMA2; outputs via STG.128
// ---------------------------------------------------------------------------
__global__ __launch_bounds__(256) void edge_gemm(
    const float* __restrict__ ef, const float* __restrict__ Wf, int E)
{
    __shared__ float xs[64 * IN_E];          // 16 KB
    const int tid = threadIdx.x;
    const int q   = tid & 31;                // cols 4q..4q+3
    const int r   = tid >> 5;                // rows r*8..r*8+8
    const long long e0 = (long long)blockIdx.x * 64;

    {   // stage 64 edge rows (row-major), streaming reads
        float4* xs4 = (float4*)xs;
        const float4* eg = (const float4*)ef;
        for (int i = tid; i < 64 * (IN_E / 4); i += 256) {
            long long row = e0 + (i >> 4);
            if (row >= E) row = E - 1;       // clamp (harmless dup)
            xs4[i] = __ldcs(&eg[row * (IN_E / 4) + (i & 15)]);
        }
    }
    __syncthreads();

    const float4* Wf4 = (const float4*)Wf;   // [64][32] float4 over cols

    float2 accL[8], accH[8];
    #pragma unroll
    for (int i = 0; i < 8; i++) {
        accL[i] = make_float2(0.f, 0.f);
        accH[i] = make_float2(0.f, 0.f);
    }

    #pragma unroll 2
    for (int k4 = 0; k4 < IN_E / 4; k4++) {
        float4 wv0 = __ldg(&Wf4[(4 * k4 + 0) * 32 + q]);
        float4 wv1 = __ldg(&Wf4[(4 * k4 + 1) * 32 + q]);
        float4 wv2 = __ldg(&Wf4[(4 * k4 + 2) * 32 + q]);
        float4 wv3 = __ldg(&Wf4[(4 * k4 + 3) * 32 + q]);
        #pragma unroll
        for (int i = 0; i < 8; i++) {
            float4 xv = *(const float4*)&xs[(r * 8 + i) * IN_E + 4 * k4]; // broadcast
            float2 x0 = make_float2(xv.x, xv.x);
            float2 x1 = make_float2(xv.y, xv.y);
            float2 x2 = make_float2(xv.z, xv.z);
            float2 x3 = make_float2(xv.w, xv.w);
            accL[i] = ffma2(x0, make_float2(wv0.x, wv0.y), accL[i]);
            accH[i] = ffma2(x0, make_float2(wv0.z, wv0.w), accH[i]);
            accL[i] = ffma2(x1, make_float2(wv1.x, wv1.y), accL[i]);
            accH[i] = ffma2(x1, make_float2(wv1.z, wv1.w), accH[i]);
            accL[i] = ffma2(x2, make_float2(wv2.x, wv2.y), accL[i]);
            accH[i] = ffma2(x2, make_float2(wv2.z, wv2.w), accH[i]);
            accL[i] = ffma2(x3, make_float2(wv3.x, wv3.y), accL[i]);
            accH[i] = ffma2(x3, make_float2(wv3.z, wv3.w), accH[i]);
        }
    }

    float4* fe4 = (float4*)g_fe;
    #pragma unroll
    for (int i = 0; i < 8; i++) {
        long long e = e0 + r * 8 + i;
        if (e < E) {
            float4 v = make_float4(accL[i].x, accL[i].y, accH[i].x, accH[i].y);
            __stcs(&fe4[e * 32 + q], v);
        }
    }
}

// ---------------------------------------------------------------------------
// 2b) fusion tail: f_out = lrelu(fe + fni[src] + fnj[dst] + bias),
//     logits to g_ex. Warp per edge, 2-edge MLP, pure streaming.
// ---------------------------------------------------------------------------
__global__ __launch_bounds__(256) void edge_tail(
    const int* __restrict__ src, const int* __restrict__ dst,
    const float* __restrict__ attn, const float* __restrict__ bias,
    float* __restrict__ fout, int E)
{
    const int lane = threadIdx.x & 31;
    const int warp = (blockIdx.x * blockDim.x + threadIdx.x) >> 5;
    const int nw = (gridDim.x * blockDim.x) >> 5;

    const float4 at4 = ((const float4*)attn)[lane]; // attn[h][f], h=lane>>3
    const float4 b4  = ((const float4*)bias)[lane];
    const float4* fe4  = (const float4*)g_fe;
    const float4* fni4 = (const float4*)g_fni;
    const float4* fnj4 = (const float4*)g_fnj;
    float4* fo4 = (float4*)fout;

    for (long long e0 = warp; e0 < E; e0 += 2LL * nw) {
        long long ee[2] = {e0, e0 + nw};
        int s[2], d[2];
        float4 fe[2], f1[2], f2[2];
        bool ok[2];
        #pragma unroll
        for (int u = 0; u < 2; u++) {
            ok[u] = (ee[u] < E);
            if (ok[u]) {
                s[u] = __ldg(&src[ee[u]]);
                d[u] = __ldg(&dst[ee[u]]);
            }
        }
        #pragma unroll
        for (int u = 0; u < 2; u++) {
            if (ok[u]) {
                fe[u] = __ldcs(&fe4[ee[u] * 32 + lane]);
                f1[u] = __ldg(&fni4[(size_t)s[u] * 32 + lane]);
                f2[u] = __ldg(&fnj4[(size_t)d[u] * 32 + lane]);
            }
        }
        #pragma unroll
        for (int u = 0; u < 2; u++) {
            if (!ok[u]) continue;
            float4 v;
            v.x = lrelu(fe[u].x + f1[u].x + f2[u].x + b4.x);
            v.y = lrelu(fe[u].y + f1[u].y + f2[u].y + b4.y);
            v.z = lrelu(fe[u].z + f1[u].z + f2[u].z + b4.z);
            v.w = lrelu(fe[u].w + f1[u].w + f2[u].w + b4.w);
            __stcs(&fo4[ee[u] * 32 + lane], v);
            float p = v.x * at4.x + v.y * at4.y + v.z * at4.z + v.w * at4.w;
            p += __shfl_xor_sync(0xffffffffu, p, 1);
            p += __shfl_xor_sync(0xffffffffu, p, 2);
            p += __shfl_xor_sync(0xffffffffu, p, 4);
            if ((lane & 7) == 0)
                g_ex[ee[u] * 4 + (lane >> 3)] = p;
        }
    }
}

// ---------------------------------------------------------------------------
// 3) fused per-node softmax + aggregation. One warp per node, no atomics.
// ---------------------------------------------------------------------------
#define AGG_WARPS 8
#define AGG_CAP 128
__global__ __launch_bounds__(256) void agg(
    const int* __restrict__ src, float* __restrict__ hout, int N)
{
    __shared__ float sa[AGG_WARPS][AGG_CAP * 4];   // exp values per edge/head
    __shared__ int   ss[AGG_WARPS][AGG_CAP];       // src ids
    const int w = threadIdx.x >> 5;
    const int lane = threadIdx.x & 31;
    const int d = blockIdx.x * AGG_WARPS + w;
    if (d >= N) return;

    const int start = g_rowptr[d];
    const int deg = g_rowptr[d + 1] - start;
    const float NEG = __int_as_float(0xff800000);   // -inf

    // phase 1a: per-head max over incoming edges
    float4 m4 = make_float4(NEG, NEG, NEG, NEG);
    for (int t = lane; t < deg; t += 32) {
        int eid = g_cidx[start + t];
        float4 l4 = *(const float4*)&g_ex[(size_t)eid * 4];
        m4.x = fmaxf(m4.x, l4.x); m4.y = fmaxf(m4.y, l4.y);
        m4.z = fmaxf(m4.z, l4.z); m4.w = fmaxf(m4.w, l4.w);
    }
    #pragma unroll
    for (int o = 16; o > 0; o >>= 1) {
        m4.x = fmaxf(m4.x, __shfl_xor_sync(0xffffffffu, m4.x, o));
        m4.y = fmaxf(m4.y, __shfl_xor_sync(0xffffffffu, m4.y, o));
        m4.z = fmaxf(m4.z, __shfl_xor_sync(0xffffffffu, m4.z, o));
        m4.w = fmaxf(m4.w, __shfl_xor_sync(0xffffffffu, m4.w, o));
    }

    // phase 1b: exp + sum, stash exp values and src ids in SMEM
    float4 s4 = make_float4(0.f, 0.f, 0.f, 0.f);
    for (int t = lane; t < deg; t += 32) {
        int eid = g_cidx[start + t];
        float4 l4 = *(const float4*)&g_ex[(size_t)eid * 4];
        float4 e4 = make_float4(__expf(l4.x - m4.x), __expf(l4.y - m4.y),
                                __expf(l4.z - m4.z), __expf(l4.w - m4.w));
        s4.x += e4.x; s4.y += e4.y; s4.z += e4.z; s4.w += e4.w;
        if (t < AGG_CAP) {
            *(float4*)&sa[w][t * 4] = e4;
            ss[w][t] = src[eid];
        }
    }
    #pragma unroll
    for (int o = 16; o > 0; o >>= 1) {
        s4.x += __shfl_xor_sync(0xffffffffu, s4.x, o);
        s4.y += __shfl_xor_sync(0xffffffffu, s4.y, o);
        s4.z += __shfl_xor_sync(0xffffffffu, s4.z, o);
        s4.w += __shfl_xor_sync(0xffffffffu, s4.w, o);
    }
    __syncwarp();

    const int head = lane >> 3;
    const float inv = __fdividef(1.0f, compsel(s4, head));
    const float mh = compsel(m4, head);

    // phase 2: aggregate h[src]*a with MLP-4 grouped gathers
    float4 acc = make_float4(0.f, 0.f, 0.f, 0.f);
    for (int t0 = 0; t0 < deg; t0 += 4) {
        int n = min(4, deg - t0);
        float a[4]; int s[4];
        #pragma unroll
        for (int r = 0; r < 4; r++) {
            if (r < n) {
                int t = t0 + r;
                if (t < AGG_CAP) {
                    a[r] = sa[w][t * 4 + head] * inv;
                    s[r] = ss[w][t];
                } else {                           // overflow fallback (rare)
                    int eid = g_cidx[start + t];
                    float4 l4 = *(const float4*)&g_ex[(size_t)eid * 4];
                    a[r] = __expf(compsel(l4, head) - mh) * inv;
                    s[r] = src[eid];
                }
            }
        }
        float4 hv[4];
        #pragma unroll
        for (int r = 0; r < 4; r++)
            if (r < n) hv[r] = __ldg(&((const float4*)(g_h + (size_t)s[r] * HFC))[lane]);
        #pragma unroll
        for (int r = 0; r < 4; r++) {
            if (r < n) {
                acc.x = fmaf(hv[r].x, a[r], acc.x);
                acc.y = fmaf(hv[r].y, a[r], acc.y);
                acc.z = fmaf(hv[r].z, a[r], acc.z);
                acc.w = fmaf(hv[r].w, a[r], acc.w);
            }
        }
    }
    ((float4*)(hout + (size_t)d * HFC))[lane] = acc;
}

// ---------------------------------------------------------------------------
extern "C" void kernel_launch(void* const* d_in, const int* in_sizes, int n_in,
                              void* d_out, int out_size)
{
    const float* nfeats = (const float*)d_in[0];
    const float* efeats = (const float*)d_in[1];
    const int*   src    = (const int*)d_in[2];
    const int*   dst    = (const int*)d_in[3];
    const float* W_node = (const float*)d_in[4];
    const float* b_node = (const float*)d_in[5];
    const float* W_ni   = (const float*)d_in[6];
    const float* W_nj   = (const float*)d_in[7];
    const float* W_fij  = (const float*)d_in[8];
    const float* attn   = (const float*)d_in[9];
    const float* bias   = (const float*)d_in[10];

    const int N = in_sizes[0] / IN_N;   // 100000
    const int E = in_sizes[2];          // 1000000

    float* h_out = (float*)d_out;                       // [N, 128]
    float* f_out = (float*)d_out + (size_t)N * HFC;     // [E, 128]

    int nb = (N + 255) / 256;

    // launch order chosen so edge_tail is the 4th launch (ncu -s capture slot)
    setup_kernel<<<512, 256>>>(W_ni, W_nj, W_node, N);            // 1
    node_proj<<<(N + 63) / 64, 128>>>(nfeats, b_node, N);         // 2
    edge_gemm<<<(E + 63) / 64, 256>>>(efeats, W_fij, E);          // 3
    edge_tail<<<148 * 8, 256>>>(src, dst, attn, bias, f_out, E);  // 4
    csr_count<<<(E + 255) / 256, 256>>>(dst, E);                  // 5
    scan_a     <<<nb, 256>>>(N);                                  // 6
    scan_b     <<<1, 512>>>(nb);                                  // 7
    scan_c     <<<nb, 256>>>(N, E);                               // 8
    csr_scatter<<<(E + 255) / 256, 256>>>(dst, E);                // 9
    agg<<<(N + AGG_WARPS - 1) / AGG_WARPS, 256>>>(src, h_out, N); // 10
}